// round 8
// baseline (speedup 1.0000x reference)
#include <cuda_runtime.h>
#include <cuda_bf16.h>
#include <cuda_fp16.h>
#include <math.h>
#include <stdint.h>

#define NN 400000
#define DD 256
#define BB 2048

// ---------------- scratch (static device globals; no allocation) ----------------
__device__ float g_hr[BB * 512];            // [h | r] per segment row
__device__ float g_c[BB * DD];              // LSTM cell state
__device__ float g_gates[BB * 1024];        // pre-activation gates
__device__ float g_b[1024];                 // bih + bhh
__device__ float g_h0[256];                 // step-1 h (same for all segments)
__device__ float g_c0[256];                 // step-1 c
__device__ int   g_seg[BB + 1];             // segment boundaries
__device__ __nv_bfloat16 g_Ah[BB * 512];    // hr hi split (bf16)
__device__ __nv_bfloat16 g_Al[BB * 512];    // hr lo split
__device__ __nv_bfloat16 g_Wh[1024 * 512];  // folded W hi split
__device__ __nv_bfloat16 g_Wl[1024 * 512];  // folded W lo split
__device__ __align__(16) __half g_x16[(size_t)NN * DD];  // fp16 cache of x (lane-permuted)

__device__ __forceinline__ float sigf(float v) { return 1.f / (1.f + __expf(-v)); }

__device__ __forceinline__ void store_split(int idx, float v) {
    __nv_bfloat16 h = __float2bfloat16(v);
    g_Ah[idx] = h;
    g_Al[idx] = __float2bfloat16(v - __bfloat162float(h));
}

// ---------------- packed fp32x2 helpers ----------------
__device__ __forceinline__ void fma2(unsigned long long& d, unsigned long long a,
                                     unsigned long long b) {
    asm("fma.rn.f32x2 %0, %1, %2, %0;" : "+l"(d) : "l"(a), "l"(b));
}
__device__ __forceinline__ unsigned long long pack2(float lo, float hi) {
    unsigned long long r;
    asm("mov.b64 %0, {%1, %2};" : "=l"(r)
        : "r"(__float_as_uint(lo)), "r"(__float_as_uint(hi)));
    return r;
}
__device__ __forceinline__ unsigned long long dup2(float v) {
    unsigned long long r;
    unsigned u = __float_as_uint(v);
    asm("mov.b64 %0, {%1, %1};" : "=l"(r) : "r"(u));
    return r;
}
__device__ __forceinline__ float2 unpack2(unsigned long long v) {
    unsigned lo, hi;
    asm("mov.b64 {%0, %1}, %2;" : "=r"(lo), "=r"(hi) : "l"(v));
    return make_float2(__uint_as_float(lo), __uint_as_float(hi));
}

// ---------------- baseline-PTX tensor helpers ----------------
__device__ __forceinline__ uint32_t smem_u32(const void* p) {
    uint32_t a;
    asm("{ .reg .u64 t; cvta.to.shared.u64 t, %1; cvt.u32.u64 %0, t; }" : "=r"(a) : "l"(p));
    return a;
}
__device__ __forceinline__ void cp_async16(uint32_t smem_dst, const void* gsrc) {
    asm volatile("cp.async.cg.shared.global [%0], [%1], 16;"
                 :: "r"(smem_dst), "l"(gsrc) : "memory");
}
#define CP_COMMIT() asm volatile("cp.async.commit_group;" ::: "memory")
#define CP_WAIT1() asm volatile("cp.async.wait_group 1;" ::: "memory")
#define CP_WAIT0() asm volatile("cp.async.wait_group 0;" ::: "memory")

__device__ __forceinline__ void ldmx4(uint32_t* r, uint32_t addr) {
    asm volatile("ldmatrix.sync.aligned.m8n8.x4.shared.b16 {%0,%1,%2,%3}, [%4];"
                 : "=r"(r[0]), "=r"(r[1]), "=r"(r[2]), "=r"(r[3]) : "r"(addr));
}
__device__ __forceinline__ void mma16816(float* c, const uint32_t* a, uint32_t b0, uint32_t b1) {
    asm volatile("mma.sync.aligned.m16n8k16.row.col.f32.bf16.bf16.f32 "
                 "{%0,%1,%2,%3}, {%4,%5,%6,%7}, {%8,%9}, {%0,%1,%2,%3};"
                 : "+f"(c[0]), "+f"(c[1]), "+f"(c[2]), "+f"(c[3])
                 : "r"(a[0]), "r"(a[1]), "r"(a[2]), "r"(a[3]), "r"(b0), "r"(b1));
}

#define SWZ(o) ((o) ^ (((o) >> 3) & 0x70))

// ---------------- prep: fold weights/bias + bf16 split + step-1 h/c ----------------
__global__ void prep_w(const float* __restrict__ Wih, const float* __restrict__ Whh,
                       const float* __restrict__ bih, const float* __restrict__ bhh) {
    int t = blockIdx.x * blockDim.x + threadIdx.x;
    if (t < 1024) g_b[t] = bih[t] + bhh[t];
    if (t < 256) {                       // step-1 h/c: q_star = h = c = 0 -> gates = b
        float bi = bih[t] + bhh[t];
        float bg = bih[512 + t] + bhh[512 + t];
        float bo = bih[768 + t] + bhh[768 + t];
        float c = sigf(bi) * tanhf(bg);
        g_c0[t] = c;
        g_h0[t] = sigf(bo) * tanhf(c);
    }
    if (t < 1024 * 512) {
        int g = t >> 9, k = t & 511;
        float v = Wih[t];
        if (k < 256) v += Whh[g * 256 + k];
        __nv_bfloat16 hi = __float2bfloat16(v);
        g_Wh[t] = hi;
        g_Wl[t] = __float2bfloat16(v - __bfloat162float(hi));
    }
}

// ---------------- segment boundaries ----------------
__global__ void seg_bounds(const int* __restrict__ idx32) {
    int b = blockIdx.x * blockDim.x + threadIdx.x;
    if (b > BB) return;
    bool is64 = (idx32[NN - 1] == 0);
    int lo = 0, hi = NN;
    while (lo < hi) {
        int mid = (lo + hi) >> 1;
        int v = is64 ? idx32[2 * mid] : idx32[mid];
        if (v < b) lo = mid + 1; else hi = mid;
    }
    g_seg[b] = lo;
}

// ---------------- shared attn combine epilogue ----------------
__device__ __forceinline__ void attn_combine(int b, int w, int lane,
                                             float m, float z, const float* rr) {
    __shared__ float sm[8], sz[8];
    __shared__ float sr[8][256];
    *(float4*)&sr[w][4 * lane]       = *(const float4*)&rr[0];
    *(float4*)&sr[w][128 + 4 * lane] = *(const float4*)&rr[4];
    if (lane == 0) { sm[w] = m; sz[w] = z; }
    __syncthreads();
    int d = threadIdx.x;
    float M = -INFINITY;
#pragma unroll
    for (int ww = 0; ww < 8; ww++) M = fmaxf(M, sm[ww]);
    float outv = 0.f;
    if (M != -INFINITY) {
        float Z = 0.f, v = 0.f;
#pragma unroll
        for (int ww = 0; ww < 8; ww++) {
            float sc = __expf(sm[ww] - M);
            Z += sc * sz[ww];
            v += sc * sr[ww][d];
        }
        outv = v / Z;
    }
    g_hr[b * 512 + 256 + d] = outv;
    store_split(b * 512 + 256 + d, outv);
}

// ---------------- attn step 1: fp32 x read, writes fp16 cache; q = h0 ----------------
__global__ void __launch_bounds__(256) attn1(const float* __restrict__ x) {
    int b = blockIdx.x;
    int s = g_seg[b], e = g_seg[b + 1];
    int lane = threadIdx.x & 31, w = threadIdx.x >> 5;

    __shared__ float q_s[256];
    {
        int d = threadIdx.x;
        float h = g_h0[d];
        g_hr[b * 512 + d] = h;
        store_split(b * 512 + d, h);
        g_c[b * 256 + d] = g_c0[d];
        q_s[d] = h;
    }
    __syncthreads();

    float4 qa = *(const float4*)&q_s[4 * lane];
    float4 qb = *(const float4*)&q_s[128 + 4 * lane];

    float m = -INFINITY, z = 0.f;
    float rr[8];
#pragma unroll
    for (int j = 0; j < 8; j++) rr[j] = 0.f;

    uint4* xc = (uint4*)g_x16;
    for (int n = s + 2 * w; n < e; n += 16) {
        const float4* x0 = (const float4*)&x[(size_t)n * DD];
        float4 xa0 = x0[lane];
        float4 xb0 = x0[32 + lane];
        bool has2 = (n + 1) < e;
        float4 xa1 = {0.f, 0.f, 0.f, 0.f}, xb1 = {0.f, 0.f, 0.f, 0.f};
        if (has2) {
            const float4* x1 = (const float4*)&x[(size_t)(n + 1) * DD];
            xa1 = x1[lane];
            xb1 = x1[32 + lane];
        }
        // write fp16 cache (lane-permuted: lane owns dims {4l..4l+3, 128+4l..128+4l+3})
        {
            uint4 pv;
            __half2* ph = (__half2*)&pv;
            ph[0] = __floats2half2_rn(xa0.x, xa0.y);
            ph[1] = __floats2half2_rn(xa0.z, xa0.w);
            ph[2] = __floats2half2_rn(xb0.x, xb0.y);
            ph[3] = __floats2half2_rn(xb0.z, xb0.w);
            xc[(size_t)n * 32 + lane] = pv;
            if (has2) {
                ph[0] = __floats2half2_rn(xa1.x, xa1.y);
                ph[1] = __floats2half2_rn(xa1.z, xa1.w);
                ph[2] = __floats2half2_rn(xb1.x, xb1.y);
                ph[3] = __floats2half2_rn(xb1.z, xb1.w);
                xc[(size_t)(n + 1) * 32 + lane] = pv;
            }
        }
        float p0 = xa0.x * qa.x + xa0.y * qa.y + xa0.z * qa.z + xa0.w * qa.w
                 + xb0.x * qb.x + xb0.y * qb.y + xb0.z * qb.z + xb0.w * qb.w;
        float p1 = xa1.x * qa.x + xa1.y * qa.y + xa1.z * qa.z + xa1.w * qa.w
                 + xb1.x * qb.x + xb1.y * qb.y + xb1.z * qb.z + xb1.w * qb.w;
#pragma unroll
        for (int o = 16; o; o >>= 1) {
            p0 += __shfl_xor_sync(0xffffffff, p0, o);
            p1 += __shfl_xor_sync(0xffffffff, p1, o);
        }
        float e1v = has2 ? p1 : -INFINITY;
        float newm = fmaxf(m, fmaxf(p0, e1v));
        float sc = __expf(m - newm);
        float a0 = __expf(p0 - newm);
        float a1 = __expf(e1v - newm);
        z = z * sc + a0 + a1;
        rr[0] = rr[0] * sc + a0 * xa0.x + a1 * xa1.x;
        rr[1] = rr[1] * sc + a0 * xa0.y + a1 * xa1.y;
        rr[2] = rr[2] * sc + a0 * xa0.z + a1 * xa1.z;
        rr[3] = rr[3] * sc + a0 * xa0.w + a1 * xa1.w;
        rr[4] = rr[4] * sc + a0 * xb0.x + a1 * xb1.x;
        rr[5] = rr[5] * sc + a0 * xb0.y + a1 * xb1.y;
        rr[6] = rr[6] * sc + a0 * xb0.z + a1 * xb1.z;
        rr[7] = rr[7] * sc + a0 * xb0.w + a1 * xb1.w;
        m = newm;
    }
    attn_combine(b, w, lane, m, z, rr);
}

// ---------------- attn steps 2/3: fused LSTM pointwise + fp16 x, 4-node unroll ------
__global__ void __launch_bounds__(256) attn23() {
    int b = blockIdx.x;
    int s = g_seg[b], e = g_seg[b + 1];
    int lane = threadIdx.x & 31, w = threadIdx.x >> 5;

    __shared__ float q_s[256];
    {
        int d = threadIdx.x;
        const float* g = g_gates + b * 1024;
        float i  = g[d]       + g_b[d];
        float f  = g[256 + d] + g_b[256 + d];
        float gg = g[512 + d] + g_b[512 + d];
        float o  = g[768 + d] + g_b[768 + d];
        float c = sigf(f) * g_c[b * 256 + d] + sigf(i) * tanhf(gg);
        g_c[b * 256 + d] = c;
        float h = sigf(o) * tanhf(c);
        g_hr[b * 512 + d] = h;
        store_split(b * 512 + d, h);
        q_s[d] = h;
    }
    __syncthreads();

    float qf[8];
    *(float4*)&qf[0] = *(const float4*)&q_s[4 * lane];
    *(float4*)&qf[4] = *(const float4*)&q_s[128 + 4 * lane];

    float m = -INFINITY, z = 0.f;
    float rr[8];
#pragma unroll
    for (int j = 0; j < 8; j++) rr[j] = 0.f;

    const uint4* xc = (const uint4*)g_x16;
    for (int n0 = s + 4 * w; n0 < e; n0 += 32) {
        float xf[4][8];
        float p[4];
#pragma unroll
        for (int i = 0; i < 4; i++) {
            int n = n0 + i;
            uint4 v = make_uint4(0u, 0u, 0u, 0u);
            if (n < e) v = xc[(size_t)n * 32 + lane];
            const __half2* ph = (const __half2*)&v;
            float2 f0 = __half22float2(ph[0]);
            float2 f1 = __half22float2(ph[1]);
            float2 f2 = __half22float2(ph[2]);
            float2 f3 = __half22float2(ph[3]);
            xf[i][0] = f0.x; xf[i][1] = f0.y; xf[i][2] = f1.x; xf[i][3] = f1.y;
            xf[i][4] = f2.x; xf[i][5] = f2.y; xf[i][6] = f3.x; xf[i][7] = f3.y;
            p[i] = xf[i][0] * qf[0] + xf[i][1] * qf[1] + xf[i][2] * qf[2] + xf[i][3] * qf[3]
                 + xf[i][4] * qf[4] + xf[i][5] * qf[5] + xf[i][6] * qf[6] + xf[i][7] * qf[7];
        }
#pragma unroll
        for (int o = 16; o; o >>= 1) {
#pragma unroll
            for (int i = 0; i < 4; i++)
                p[i] += __shfl_xor_sync(0xffffffff, p[i], o);
        }
        float e0 = p[0];
        float e1 = (n0 + 1 < e) ? p[1] : -INFINITY;
        float e2 = (n0 + 2 < e) ? p[2] : -INFINITY;
        float e3 = (n0 + 3 < e) ? p[3] : -INFINITY;
        float newm = fmaxf(m, fmaxf(fmaxf(e0, e1), fmaxf(e2, e3)));
        float sc = __expf(m - newm);
        float a0 = __expf(e0 - newm);
        float a1 = __expf(e1 - newm);
        float a2 = __expf(e2 - newm);
        float a3 = __expf(e3 - newm);
        z = z * sc + a0 + a1 + a2 + a3;
#pragma unroll
        for (int j = 0; j < 8; j++)
            rr[j] = rr[j] * sc + a0 * xf[0][j] + a1 * xf[1][j] + a2 * xf[2][j] + a3 * xf[3][j];
        m = newm;
    }
    attn_combine(b, w, lane, m, z, rr);
}

// ---------------- gates GEMM via mma.sync bf16 (HMMA), split-precision K=1536 ----------
// C[m][n] = Ah·Wh + Al·Wh + Ah·Wl. CTA tile 128x64 -> grid (16,16)=256 CTAs,
// 2 CTAs/SM resident (72KB smem, ~90 regs). 24 chunks of K=64, 3-stage cp.async.
// 8 warps: 4(m) x 2(n), warp tile 32x32.
__global__ void __launch_bounds__(256) gemm_gates_mma() {
    extern __shared__ char dsm[];   // 3 stages x (16KB A + 8KB B) = 72KB

    int tid = threadIdx.x, wid = tid >> 5, lane = tid & 31;
    int bm = blockIdx.y * 128, bn = blockIdx.x * 64;

    const __nv_bfloat16* Asrcs[3] = { g_Ah, g_Al, g_Ah };
    const __nv_bfloat16* Bsrcs[3] = { g_Wh, g_Wh, g_Wl };

    // A loader: 2 threads/row (128 rows), 64B each.  B loader: 4 threads/row (64 rows), 32B each.
    int arow = tid >> 1, ahalf = tid & 1;
    int abase = arow * 128 + ahalf * 64;
    int brow = tid >> 2, bq = tid & 3;
    int bbase = brow * 128 + bq * 32;

    float acc[2][4][4];
#pragma unroll
    for (int i = 0; i < 2; i++)
#pragma unroll
        for (int j = 0; j < 4; j++)
#pragma unroll
            for (int q = 0; q < 4; q++) acc[i][j][q] = 0.f;

    auto issue = [&](int c, int st) {
        int kb = (c & 7) * 64;
        const __nv_bfloat16* As = Asrcs[c >> 3] + (size_t)(bm + arow) * 512 + kb + ahalf * 32;
        const __nv_bfloat16* Bs = Bsrcs[c >> 3] + (size_t)(bn + brow) * 512 + kb + bq * 16;
        uint32_t ua = smem_u32(dsm + st * 24576);
        uint32_t ub = ua + 16384;
#pragma unroll
        for (int j = 0; j < 4; j++)
            cp_async16(ua + SWZ(abase + j * 16), (const char*)As + j * 16);
#pragma unroll
        for (int j = 0; j < 2; j++)
            cp_async16(ub + SWZ(bbase + j * 16), (const char*)Bs + j * 16);
        CP_COMMIT();
    };

    issue(0, 0);
    issue(1, 1);

    int wm = (wid >> 1) * 32;      // 4 m-tiles of 32
    int wn = (wid & 1) * 32;       // 2 n-tiles of 32
    int a_row = (lane & 7) + 8 * ((lane >> 3) & 1);
    int a_colB = (lane >> 4) * 16;
    int b_row = ((lane >> 4) << 3) + (lane & 7);
    int b_colB = ((lane >> 3) & 1) * 16;

    for (int c = 0; c < 24; c++) {
        if (c == 23) { CP_WAIT0(); } else { CP_WAIT1(); }
        __syncthreads();
        if (c + 2 < 24) issue(c + 2, (c + 2) % 3);
        uint32_t ua = smem_u32(dsm + (c % 3) * 24576);
        uint32_t ub = ua + 16384;
#pragma unroll
        for (int kk = 0; kk < 4; kk++) {
            int kB = kk * 32;
            uint32_t a[2][4];
#pragma unroll
            for (int mt = 0; mt < 2; mt++)
                ldmx4(a[mt], ua + SWZ((wm + mt * 16 + a_row) * 128 + a_colB + kB));
            uint32_t bfr[2][4];
#pragma unroll
            for (int nt = 0; nt < 2; nt++)
                ldmx4(bfr[nt], ub + SWZ((wn + nt * 16 + b_row) * 128 + b_colB + kB));
#pragma unroll
            for (int mt = 0; mt < 2; mt++) {
#pragma unroll
                for (int nt = 0; nt < 4; nt++) {
                    uint32_t b0 = bfr[nt >> 1][(nt & 1) * 2];
                    uint32_t b1 = bfr[nt >> 1][(nt & 1) * 2 + 1];
                    mma16816(acc[mt][nt], a[mt], b0, b1);
                }
            }
        }
    }

    __syncthreads();
    int g = lane >> 2, n0 = (lane & 3) * 2;
#pragma unroll
    for (int mt = 0; mt < 2; mt++) {
#pragma unroll
        for (int nt = 0; nt < 4; nt++) {
            int row = bm + wm + mt * 16 + g;
            int col = bn + wn + nt * 8 + n0;
            *(float2*)&g_gates[(size_t)row * 1024 + col] =
                make_float2(acc[mt][nt][0], acc[mt][nt][1]);
            *(float2*)&g_gates[(size_t)(row + 8) * 1024 + col] =
                make_float2(acc[mt][nt][2], acc[mt][nt][3]);
        }
    }
}

// ---------------- output GEMM: 64x64 tile, BK=8, f32x2 ----------------
__global__ void __launch_bounds__(256) gemm_out64(const float* __restrict__ Wp,
                                                  const float* __restrict__ bp,
                                                  float* __restrict__ out) {
    const int K = 512, LDC = 256;
    __shared__ float As[2][8][68];
    __shared__ float Bs[2][8][68];
    int tid = threadIdx.x;
    int bm = blockIdx.y * 64, bn = blockIdx.x * 64;
    int lr = tid >> 2, lc = (tid & 3) << 1;
    int tx = tid & 15, ty = tid >> 4;
    const float* Ag = g_hr + (size_t)(bm + lr) * K + lc;
    const float* Bg = Wp + (size_t)(bn + lr) * K + lc;

    unsigned long long acc[2][4];
#pragma unroll
    for (int i = 0; i < 2; i++)
#pragma unroll
        for (int j = 0; j < 4; j++) acc[i][j] = 0ull;

    float2 a2 = *(const float2*)Ag;
    float2 b2 = *(const float2*)Bg;
    As[0][lc][lr] = a2.x; As[0][lc + 1][lr] = a2.y;
    Bs[0][lc][lr] = b2.x; Bs[0][lc + 1][lr] = b2.y;
    __syncthreads();

    int buf = 0;
    for (int k0 = 0; k0 < K; k0 += 8) {
        bool more = (k0 + 8) < K;
        if (more) {
            a2 = *(const float2*)(Ag + k0 + 8);
            b2 = *(const float2*)(Bg + k0 + 8);
        }
#pragma unroll
        for (int k = 0; k < 8; k++) {
            float4 a0 = *(const float4*)&As[buf][k][ty * 4];
            float4 b0 = *(const float4*)&Bs[buf][k][tx * 4];
            unsigned long long ap[2] = { pack2(a0.x, a0.y), pack2(a0.z, a0.w) };
            unsigned long long bd[4] = { dup2(b0.x), dup2(b0.y), dup2(b0.z), dup2(b0.w) };
#pragma unroll
            for (int i = 0; i < 2; i++)
#pragma unroll
                for (int j = 0; j < 4; j++)
                    fma2(acc[i][j], ap[i], bd[j]);
        }
        if (more) {
            As[buf ^ 1][lc][lr] = a2.x; As[buf ^ 1][lc + 1][lr] = a2.y;
            Bs[buf ^ 1][lc][lr] = b2.x; Bs[buf ^ 1][lc + 1][lr] = b2.y;
        }
        __syncthreads();
        buf ^= 1;
    }

    float4 bias4 = *(const float4*)&bp[bn + tx * 4];
    int rbase[2] = { ty * 4, ty * 4 + 2 };
#pragma unroll
    for (int i = 0; i < 2; i++) {
        float4 lo, hi;
        float2 u;
        u = unpack2(acc[i][0]); lo.x = u.x; hi.x = u.y;
        u = unpack2(acc[i][1]); lo.y = u.x; hi.y = u.y;
        u = unpack2(acc[i][2]); lo.z = u.x; hi.z = u.y;
        u = unpack2(acc[i][3]); lo.w = u.x; hi.w = u.y;
        lo.x += bias4.x; lo.y += bias4.y; lo.z += bias4.z; lo.w += bias4.w;
        hi.x += bias4.x; hi.y += bias4.y; hi.z += bias4.z; hi.w += bias4.w;
        int r0 = bm + rbase[i];
        *(float4*)&out[(size_t)r0 * LDC + bn + tx * 4] = lo;
        *(float4*)&out[(size_t)(r0 + 1) * LDC + bn + tx * 4] = hi;
    }
}

// ---------------- launch ----------------
extern "C" void kernel_launch(void* const* d_in, const int* in_sizes, int n_in,
                              void* d_out, int out_size) {
    const float* x     = (const float*)d_in[0];
    const int*   idx32 = (const int*)d_in[1];
    const float* Wih   = (const float*)d_in[2];
    const float* Whh   = (const float*)d_in[3];
    const float* bih   = (const float*)d_in[4];
    const float* bhh   = (const float*)d_in[5];
    const float* Wp    = (const float*)d_in[6];
    const float* bp    = (const float*)d_in[7];
    float* out = (float*)d_out;

    const int GEMM_DSM = 3 * 24576;   // 72 KB
    cudaFuncSetAttribute(gemm_gates_mma, cudaFuncAttributeMaxDynamicSharedMemorySize, GEMM_DSM);

    prep_w<<<(1024 * 512 + 255) / 256, 256>>>(Wih, Whh, bih, bhh);
    seg_bounds<<<(BB + 1 + 255) / 256, 256>>>(idx32);
    attn1<<<BB, 256>>>(x);                                  // step 1 + fp16 cache fill

    for (int t = 0; t < 2; t++) {                           // steps 2, 3
        gemm_gates_mma<<<dim3(16, 16), 256, GEMM_DSM>>>();
        attn23<<<BB, 256>>>();
    }
    gemm_out64<<<dim3(4, 32), 256>>>(Wp, bp, out);
}

// round 9
// speedup vs baseline: 1.0845x; 1.0845x over previous
#include <cuda_runtime.h>
#include <cuda_fp16.h>
#include <math.h>
#include <stdint.h>

#define NN 400000
#define DD 256
#define BB 2048

// ---------------- scratch (static device globals; no allocation) ----------------
__device__ float g_hr[BB * 512];            // [h | r] per segment row
__device__ float g_c[BB * DD];              // LSTM cell state
__device__ float g_gates[BB * 1024];        // pre-activation gates
__device__ float g_b[1024];                 // bih + bhh
__device__ float g_h0[256];                 // step-1 h (same for all segments)
__device__ float g_c0[256];                 // step-1 c
__device__ int   g_seg[BB + 1];             // segment boundaries
__device__ __half g_Ah[BB * 512];           // hr hi split (fp16)
__device__ __half g_Al[BB * 512];           // hr lo split (fp16 residual)
__device__ __half g_Wh[1024 * 512];         // folded W (fp16)
__device__ __align__(16) __half g_x16[(size_t)NN * DD];  // fp16 cache of x (lane-permuted)

__device__ __forceinline__ float sigf(float v) { return 1.f / (1.f + __expf(-v)); }

__device__ __forceinline__ void store_split(int idx, float v) {
    __half h = __float2half_rn(v);
    g_Ah[idx] = h;
    g_Al[idx] = __float2half_rn(v - __half2float(h));
}

// ---------------- packed fp32x2 helpers ----------------
__device__ __forceinline__ void fma2(unsigned long long& d, unsigned long long a,
                                     unsigned long long b) {
    asm("fma.rn.f32x2 %0, %1, %2, %0;" : "+l"(d) : "l"(a), "l"(b));
}
__device__ __forceinline__ unsigned long long pack2(float lo, float hi) {
    unsigned long long r;
    asm("mov.b64 %0, {%1, %2};" : "=l"(r)
        : "r"(__float_as_uint(lo)), "r"(__float_as_uint(hi)));
    return r;
}
__device__ __forceinline__ unsigned long long dup2(float v) {
    unsigned long long r;
    unsigned u = __float_as_uint(v);
    asm("mov.b64 %0, {%1, %1};" : "=l"(r) : "r"(u));
    return r;
}
__device__ __forceinline__ float2 unpack2(unsigned long long v) {
    unsigned lo, hi;
    asm("mov.b64 {%0, %1}, %2;" : "=r"(lo), "=r"(hi) : "l"(v));
    return make_float2(__uint_as_float(lo), __uint_as_float(hi));
}

// ---------------- baseline-PTX tensor helpers ----------------
__device__ __forceinline__ uint32_t smem_u32(const void* p) {
    uint32_t a;
    asm("{ .reg .u64 t; cvta.to.shared.u64 t, %1; cvt.u32.u64 %0, t; }" : "=r"(a) : "l"(p));
    return a;
}
__device__ __forceinline__ void cp_async16(uint32_t smem_dst, const void* gsrc) {
    asm volatile("cp.async.cg.shared.global [%0], [%1], 16;"
                 :: "r"(smem_dst), "l"(gsrc) : "memory");
}
#define CP_COMMIT() asm volatile("cp.async.commit_group;" ::: "memory")
#define CP_WAIT1() asm volatile("cp.async.wait_group 1;" ::: "memory")
#define CP_WAIT0() asm volatile("cp.async.wait_group 0;" ::: "memory")

__device__ __forceinline__ void ldmx4(uint32_t* r, uint32_t addr) {
    asm volatile("ldmatrix.sync.aligned.m8n8.x4.shared.b16 {%0,%1,%2,%3}, [%4];"
                 : "=r"(r[0]), "=r"(r[1]), "=r"(r[2]), "=r"(r[3]) : "r"(addr));
}
__device__ __forceinline__ void mma16816(float* c, const uint32_t* a, uint32_t b0, uint32_t b1) {
    asm volatile("mma.sync.aligned.m16n8k16.row.col.f32.f16.f16.f32 "
                 "{%0,%1,%2,%3}, {%4,%5,%6,%7}, {%8,%9}, {%0,%1,%2,%3};"
                 : "+f"(c[0]), "+f"(c[1]), "+f"(c[2]), "+f"(c[3])
                 : "r"(a[0]), "r"(a[1]), "r"(a[2]), "r"(a[3]), "r"(b0), "r"(b1));
}

#define SWZ(o) ((o) ^ (((o) >> 3) & 0x70))

// ---------------- prep: fold weights/bias + fp16 convert + step-1 h/c ----------------
__global__ void prep_w(const float* __restrict__ Wih, const float* __restrict__ Whh,
                       const float* __restrict__ bih, const float* __restrict__ bhh) {
    int t = blockIdx.x * blockDim.x + threadIdx.x;
    if (t < 1024) g_b[t] = bih[t] + bhh[t];
    if (t < 256) {                       // step-1 h/c: q_star = h = c = 0 -> gates = b
        float bi = bih[t] + bhh[t];
        float bg = bih[512 + t] + bhh[512 + t];
        float bo = bih[768 + t] + bhh[768 + t];
        float c = sigf(bi) * tanhf(bg);
        g_c0[t] = c;
        g_h0[t] = sigf(bo) * tanhf(c);
    }
    if (t < 1024 * 512) {
        int g = t >> 9, k = t & 511;
        float v = Wih[t];
        if (k < 256) v += Whh[g * 256 + k];
        g_Wh[t] = __float2half_rn(v);
    }
}

// ---------------- segment boundaries ----------------
__global__ void seg_bounds(const int* __restrict__ idx32) {
    int b = blockIdx.x * blockDim.x + threadIdx.x;
    if (b > BB) return;
    bool is64 = (idx32[NN - 1] == 0);
    int lo = 0, hi = NN;
    while (lo < hi) {
        int mid = (lo + hi) >> 1;
        int v = is64 ? idx32[2 * mid] : idx32[mid];
        if (v < b) lo = mid + 1; else hi = mid;
    }
    g_seg[b] = lo;
}

// ---------------- shared attn combine epilogue ----------------
__device__ __forceinline__ void attn_combine(int b, int w, int lane,
                                             float m, float z, const float* rr) {
    __shared__ float sm[8], sz[8];
    __shared__ float sr[8][256];
    *(float4*)&sr[w][4 * lane]       = *(const float4*)&rr[0];
    *(float4*)&sr[w][128 + 4 * lane] = *(const float4*)&rr[4];
    if (lane == 0) { sm[w] = m; sz[w] = z; }
    __syncthreads();
    int d = threadIdx.x;
    float M = -INFINITY;
#pragma unroll
    for (int ww = 0; ww < 8; ww++) M = fmaxf(M, sm[ww]);
    float outv = 0.f;
    if (M != -INFINITY) {
        float Z = 0.f, v = 0.f;
#pragma unroll
        for (int ww = 0; ww < 8; ww++) {
            float sc = __expf(sm[ww] - M);
            Z += sc * sz[ww];
            v += sc * sr[ww][d];
        }
        outv = v / Z;
    }
    g_hr[b * 512 + 256 + d] = outv;
    store_split(b * 512 + 256 + d, outv);
}

// ---------------- attn step 1: fp32 x read, writes fp16 cache; q = h0 ----------------
__global__ void __launch_bounds__(256) attn1(const float* __restrict__ x) {
    int b = blockIdx.x;
    int s = g_seg[b], e = g_seg[b + 1];
    int lane = threadIdx.x & 31, w = threadIdx.x >> 5;

    __shared__ float q_s[256];
    {
        int d = threadIdx.x;
        float h = g_h0[d];
        g_hr[b * 512 + d] = h;
        store_split(b * 512 + d, h);
        g_c[b * 256 + d] = g_c0[d];
        q_s[d] = h;
    }
    __syncthreads();

    float4 qa = *(const float4*)&q_s[4 * lane];
    float4 qb = *(const float4*)&q_s[128 + 4 * lane];

    float m = -INFINITY, z = 0.f;
    float rr[8];
#pragma unroll
    for (int j = 0; j < 8; j++) rr[j] = 0.f;

    uint4* xc = (uint4*)g_x16;
    for (int n = s + 2 * w; n < e; n += 16) {
        const float4* x0 = (const float4*)&x[(size_t)n * DD];
        float4 xa0 = x0[lane];
        float4 xb0 = x0[32 + lane];
        bool has2 = (n + 1) < e;
        float4 xa1 = {0.f, 0.f, 0.f, 0.f}, xb1 = {0.f, 0.f, 0.f, 0.f};
        if (has2) {
            const float4* x1 = (const float4*)&x[(size_t)(n + 1) * DD];
            xa1 = x1[lane];
            xb1 = x1[32 + lane];
        }
        // write fp16 cache (lane-permuted: lane owns dims {4l..4l+3, 128+4l..128+4l+3})
        {
            uint4 pv;
            __half2* ph = (__half2*)&pv;
            ph[0] = __floats2half2_rn(xa0.x, xa0.y);
            ph[1] = __floats2half2_rn(xa0.z, xa0.w);
            ph[2] = __floats2half2_rn(xb0.x, xb0.y);
            ph[3] = __floats2half2_rn(xb0.z, xb0.w);
            xc[(size_t)n * 32 + lane] = pv;
            if (has2) {
                ph[0] = __floats2half2_rn(xa1.x, xa1.y);
                ph[1] = __floats2half2_rn(xa1.z, xa1.w);
                ph[2] = __floats2half2_rn(xb1.x, xb1.y);
                ph[3] = __floats2half2_rn(xb1.z, xb1.w);
                xc[(size_t)(n + 1) * 32 + lane] = pv;
            }
        }
        float p0 = xa0.x * qa.x + xa0.y * qa.y + xa0.z * qa.z + xa0.w * qa.w
                 + xb0.x * qb.x + xb0.y * qb.y + xb0.z * qb.z + xb0.w * qb.w;
        float p1 = xa1.x * qa.x + xa1.y * qa.y + xa1.z * qa.z + xa1.w * qa.w
                 + xb1.x * qb.x + xb1.y * qb.y + xb1.z * qb.z + xb1.w * qb.w;
#pragma unroll
        for (int o = 16; o; o >>= 1) {
            p0 += __shfl_xor_sync(0xffffffff, p0, o);
            p1 += __shfl_xor_sync(0xffffffff, p1, o);
        }
        float e1v = has2 ? p1 : -INFINITY;
        float newm = fmaxf(m, fmaxf(p0, e1v));
        float sc = __expf(m - newm);
        float a0 = __expf(p0 - newm);
        float a1 = __expf(e1v - newm);
        z = z * sc + a0 + a1;
        rr[0] = rr[0] * sc + a0 * xa0.x + a1 * xa1.x;
        rr[1] = rr[1] * sc + a0 * xa0.y + a1 * xa1.y;
        rr[2] = rr[2] * sc + a0 * xa0.z + a1 * xa1.z;
        rr[3] = rr[3] * sc + a0 * xa0.w + a1 * xa1.w;
        rr[4] = rr[4] * sc + a0 * xb0.x + a1 * xb1.x;
        rr[5] = rr[5] * sc + a0 * xb0.y + a1 * xb1.y;
        rr[6] = rr[6] * sc + a0 * xb0.z + a1 * xb1.z;
        rr[7] = rr[7] * sc + a0 * xb0.w + a1 * xb1.w;
        m = newm;
    }
    attn_combine(b, w, lane, m, z, rr);
}

// ---------------- attn steps 2/3: fused LSTM pointwise + fp16 x, 4-node unroll ------
__global__ void __launch_bounds__(256) attn23() {
    int b = blockIdx.x;
    int s = g_seg[b], e = g_seg[b + 1];
    int lane = threadIdx.x & 31, w = threadIdx.x >> 5;

    __shared__ float q_s[256];
    {
        int d = threadIdx.x;
        const float* g = g_gates + b * 1024;
        float i  = g[d]       + g_b[d];
        float f  = g[256 + d] + g_b[256 + d];
        float gg = g[512 + d] + g_b[512 + d];
        float o  = g[768 + d] + g_b[768 + d];
        float c = sigf(f) * g_c[b * 256 + d] + sigf(i) * tanhf(gg);
        g_c[b * 256 + d] = c;
        float h = sigf(o) * tanhf(c);
        g_hr[b * 512 + d] = h;
        store_split(b * 512 + d, h);
        q_s[d] = h;
    }
    __syncthreads();

    float qf[8];
    *(float4*)&qf[0] = *(const float4*)&q_s[4 * lane];
    *(float4*)&qf[4] = *(const float4*)&q_s[128 + 4 * lane];

    float m = -INFINITY, z = 0.f;
    float rr[8];
#pragma unroll
    for (int j = 0; j < 8; j++) rr[j] = 0.f;

    const uint4* xc = (const uint4*)g_x16;
    for (int n0 = s + 4 * w; n0 < e; n0 += 32) {
        float xf[4][8];
        float p[4];
#pragma unroll
        for (int i = 0; i < 4; i++) {
            int n = n0 + i;
            uint4 v = make_uint4(0u, 0u, 0u, 0u);
            if (n < e) v = xc[(size_t)n * 32 + lane];
            const __half2* ph = (const __half2*)&v;
            float2 f0 = __half22float2(ph[0]);
            float2 f1 = __half22float2(ph[1]);
            float2 f2 = __half22float2(ph[2]);
            float2 f3 = __half22float2(ph[3]);
            xf[i][0] = f0.x; xf[i][1] = f0.y; xf[i][2] = f1.x; xf[i][3] = f1.y;
            xf[i][4] = f2.x; xf[i][5] = f2.y; xf[i][6] = f3.x; xf[i][7] = f3.y;
            p[i] = xf[i][0] * qf[0] + xf[i][1] * qf[1] + xf[i][2] * qf[2] + xf[i][3] * qf[3]
                 + xf[i][4] * qf[4] + xf[i][5] * qf[5] + xf[i][6] * qf[6] + xf[i][7] * qf[7];
        }
#pragma unroll
        for (int o = 16; o; o >>= 1) {
#pragma unroll
            for (int i = 0; i < 4; i++)
                p[i] += __shfl_xor_sync(0xffffffff, p[i], o);
        }
        float e0 = p[0];
        float e1 = (n0 + 1 < e) ? p[1] : -INFINITY;
        float e2 = (n0 + 2 < e) ? p[2] : -INFINITY;
        float e3 = (n0 + 3 < e) ? p[3] : -INFINITY;
        float newm = fmaxf(m, fmaxf(fmaxf(e0, e1), fmaxf(e2, e3)));
        float sc = __expf(m - newm);
        float a0 = __expf(e0 - newm);
        float a1 = __expf(e1 - newm);
        float a2 = __expf(e2 - newm);
        float a3 = __expf(e3 - newm);
        z = z * sc + a0 + a1 + a2 + a3;
#pragma unroll
        for (int j = 0; j < 8; j++)
            rr[j] = rr[j] * sc + a0 * xf[0][j] + a1 * xf[1][j] + a2 * xf[2][j] + a3 * xf[3][j];
        m = newm;
    }
    attn_combine(b, w, lane, m, z, rr);
}

// ---------------- gates GEMM via mma.sync fp16 (HMMA), 2-term split K=1024 ----------
// C[m][n] = Ah16·Wh16 + Al16·Wh16. CTA tile 128x128, 16 chunks of K=64, cp.async
// 3-stage pipeline, one __syncthreads per chunk. 8 warps: 2(m) x 4(n).
__global__ void __launch_bounds__(256) gemm_gates_mma() {
    extern __shared__ char dsm[];   // 3 stages x (16KB A + 16KB B)

    int tid = threadIdx.x, wid = tid >> 5, lane = tid & 31;
    int bm = blockIdx.y * 128, bn = blockIdx.x * 128;

    const __half* Asrcs[2] = { g_Ah, g_Al };

    int srow = tid >> 1, shalf = tid & 1;
    int sbase = srow * 128 + shalf * 64;

    float acc[4][4][4];
#pragma unroll
    for (int i = 0; i < 4; i++)
#pragma unroll
        for (int j = 0; j < 4; j++)
#pragma unroll
            for (int q = 0; q < 4; q++) acc[i][j][q] = 0.f;

    auto issue = [&](int c, int st) {
        int kb = (c & 7) * 64;
        const __half* As = Asrcs[c >> 3] + (size_t)(bm + srow) * 512 + kb + shalf * 32;
        const __half* Bs = g_Wh + (size_t)(bn + srow) * 512 + kb + shalf * 32;
        uint32_t ua = smem_u32(dsm + st * 32768);
        uint32_t ub = ua + 16384;
#pragma unroll
        for (int j = 0; j < 4; j++) {
            cp_async16(ua + SWZ(sbase + j * 16), (const char*)As + j * 16);
            cp_async16(ub + SWZ(sbase + j * 16), (const char*)Bs + j * 16);
        }
        CP_COMMIT();
    };

    issue(0, 0);
    issue(1, 1);

    int wm = (wid >> 2) * 64;
    int wn = (wid & 3) * 32;
    int a_row = (lane & 7) + 8 * ((lane >> 3) & 1);
    int a_colB = (lane >> 4) * 16;
    int b_row = ((lane >> 4) << 3) + (lane & 7);
    int b_colB = ((lane >> 3) & 1) * 16;

    for (int c = 0; c < 16; c++) {
        if (c == 15) { CP_WAIT0(); } else { CP_WAIT1(); }
        __syncthreads();
        if (c + 2 < 16) issue(c + 2, (c + 2) % 3);
        uint32_t ua = smem_u32(dsm + (c % 3) * 32768);
        uint32_t ub = ua + 16384;
#pragma unroll
        for (int kk = 0; kk < 4; kk++) {
            int kB = kk * 32;
            uint32_t a[4][4];
#pragma unroll
            for (int mt = 0; mt < 4; mt++)
                ldmx4(a[mt], ua + SWZ((wm + mt * 16 + a_row) * 128 + a_colB + kB));
            uint32_t bfr[2][4];
#pragma unroll
            for (int nt = 0; nt < 2; nt++)
                ldmx4(bfr[nt], ub + SWZ((wn + nt * 16 + b_row) * 128 + b_colB + kB));
#pragma unroll
            for (int mt = 0; mt < 4; mt++) {
#pragma unroll
                for (int nt = 0; nt < 4; nt++) {
                    uint32_t b0 = bfr[nt >> 1][(nt & 1) * 2];
                    uint32_t b1 = bfr[nt >> 1][(nt & 1) * 2 + 1];
                    mma16816(acc[mt][nt], a[mt], b0, b1);
                }
            }
        }
    }

    __syncthreads();
    int g = lane >> 2, n0 = (lane & 3) * 2;
#pragma unroll
    for (int mt = 0; mt < 4; mt++) {
#pragma unroll
        for (int nt = 0; nt < 4; nt++) {
            int row = bm + wm + mt * 16 + g;
            int col = bn + wn + nt * 8 + n0;
            *(float2*)&g_gates[(size_t)row * 1024 + col] =
                make_float2(acc[mt][nt][0], acc[mt][nt][1]);
            *(float2*)&g_gates[(size_t)(row + 8) * 1024 + col] =
                make_float2(acc[mt][nt][2], acc[mt][nt][3]);
        }
    }
}

// ---------------- output GEMM: 64x64 tile, BK=8, f32x2 ----------------
__global__ void __launch_bounds__(256) gemm_out64(const float* __restrict__ Wp,
                                                  const float* __restrict__ bp,
                                                  float* __restrict__ out) {
    const int K = 512, LDC = 256;
    __shared__ float As[2][8][68];
    __shared__ float Bs[2][8][68];
    int tid = threadIdx.x;
    int bm = blockIdx.y * 64, bn = blockIdx.x * 64;
    int lr = tid >> 2, lc = (tid & 3) << 1;
    int tx = tid & 15, ty = tid >> 4;
    const float* Ag = g_hr + (size_t)(bm + lr) * K + lc;
    const float* Bg = Wp + (size_t)(bn + lr) * K + lc;

    unsigned long long acc[2][4];
#pragma unroll
    for (int i = 0; i < 2; i++)
#pragma unroll
        for (int j = 0; j < 4; j++) acc[i][j] = 0ull;

    float2 a2 = *(const float2*)Ag;
    float2 b2 = *(const float2*)Bg;
    As[0][lc][lr] = a2.x; As[0][lc + 1][lr] = a2.y;
    Bs[0][lc][lr] = b2.x; Bs[0][lc + 1][lr] = b2.y;
    __syncthreads();

    int buf = 0;
    for (int k0 = 0; k0 < K; k0 += 8) {
        bool more = (k0 + 8) < K;
        if (more) {
            a2 = *(const float2*)(Ag + k0 + 8);
            b2 = *(const float2*)(Bg + k0 + 8);
        }
#pragma unroll
        for (int k = 0; k < 8; k++) {
            float4 a0 = *(const float4*)&As[buf][k][ty * 4];
            float4 b0 = *(const float4*)&Bs[buf][k][tx * 4];
            unsigned long long ap[2] = { pack2(a0.x, a0.y), pack2(a0.z, a0.w) };
            unsigned long long bd[4] = { dup2(b0.x), dup2(b0.y), dup2(b0.z), dup2(b0.w) };
#pragma unroll
            for (int i = 0; i < 2; i++)
#pragma unroll
                for (int j = 0; j < 4; j++)
                    fma2(acc[i][j], ap[i], bd[j]);
        }
        if (more) {
            As[buf ^ 1][lc][lr] = a2.x; As[buf ^ 1][lc + 1][lr] = a2.y;
            Bs[buf ^ 1][lc][lr] = b2.x; Bs[buf ^ 1][lc + 1][lr] = b2.y;
        }
        __syncthreads();
        buf ^= 1;
    }

    float4 bias4 = *(const float4*)&bp[bn + tx * 4];
    int rbase[2] = { ty * 4, ty * 4 + 2 };
#pragma unroll
    for (int i = 0; i < 2; i++) {
        float4 lo, hi;
        float2 u;
        u = unpack2(acc[i][0]); lo.x = u.x; hi.x = u.y;
        u = unpack2(acc[i][1]); lo.y = u.x; hi.y = u.y;
        u = unpack2(acc[i][2]); lo.z = u.x; hi.z = u.y;
        u = unpack2(acc[i][3]); lo.w = u.x; hi.w = u.y;
        lo.x += bias4.x; lo.y += bias4.y; lo.z += bias4.z; lo.w += bias4.w;
        hi.x += bias4.x; hi.y += bias4.y; hi.z += bias4.z; hi.w += bias4.w;
        int r0 = bm + rbase[i];
        *(float4*)&out[(size_t)r0 * LDC + bn + tx * 4] = lo;
        *(float4*)&out[(size_t)(r0 + 1) * LDC + bn + tx * 4] = hi;
    }
}

// ---------------- launch ----------------
extern "C" void kernel_launch(void* const* d_in, const int* in_sizes, int n_in,
                              void* d_out, int out_size) {
    const float* x     = (const float*)d_in[0];
    const int*   idx32 = (const int*)d_in[1];
    const float* Wih   = (const float*)d_in[2];
    const float* Whh   = (const float*)d_in[3];
    const float* bih   = (const float*)d_in[4];
    const float* bhh   = (const float*)d_in[5];
    const float* Wp    = (const float*)d_in[6];
    const float* bp    = (const float*)d_in[7];
    float* out = (float*)d_out;

    const int GEMM_DSM = 3 * 32768;   // 96 KB
    cudaFuncSetAttribute(gemm_gates_mma, cudaFuncAttributeMaxDynamicSharedMemorySize, GEMM_DSM);

    prep_w<<<(1024 * 512 + 255) / 256, 256>>>(Wih, Whh, bih, bhh);
    seg_bounds<<<(BB + 1 + 255) / 256, 256>>>(idx32);
    attn1<<<BB, 256>>>(x);                                  // step 1 + fp16 cache fill

    for (int t = 0; t < 2; t++) {                           // steps 2, 3
        gemm_gates_mma<<<dim3(8, 16), 256, GEMM_DSM>>>();
        attn23<<<BB, 256>>>();
    }
    gemm_out64<<<dim3(4, 32), 256>>>(Wp, bp, out);
}

// round 10
// speedup vs baseline: 1.1955x; 1.1023x over previous
#include <cuda_runtime.h>
#include <cuda_fp16.h>
#include <math.h>
#include <stdint.h>

#define NN 400000
#define DD 256
#define BB 2048

// ---------------- scratch (static device globals; no allocation) ----------------
__device__ float g_hr[BB * 512];            // [h | r] per segment row
__device__ float g_c[BB * DD];              // LSTM cell state
__device__ float g_gates[BB * 1024];        // pre-activation gates
__device__ float g_b[1024];                 // bih + bhh
__device__ float g_h0[256];                 // step-1 h (same for all segments)
__device__ float g_c0[256];                 // step-1 c
__device__ int   g_seg[BB + 1];             // segment boundaries
__device__ __half g_Ah[BB * 512];           // hr (fp16) for HMMA
__device__ __half g_Wh[1024 * 512];         // folded W (fp16)
__device__ __align__(16) __half g_x16[(size_t)NN * DD];  // fp16 cache of x (lane-permuted)

__device__ __forceinline__ float sigf(float v) { return 1.f / (1.f + __expf(-v)); }

// ---------------- packed fp32x2 helpers ----------------
__device__ __forceinline__ void fma2(unsigned long long& d, unsigned long long a,
                                     unsigned long long b) {
    asm("fma.rn.f32x2 %0, %1, %2, %0;" : "+l"(d) : "l"(a), "l"(b));
}
__device__ __forceinline__ unsigned long long pack2(float lo, float hi) {
    unsigned long long r;
    asm("mov.b64 %0, {%1, %2};" : "=l"(r)
        : "r"(__float_as_uint(lo)), "r"(__float_as_uint(hi)));
    return r;
}
__device__ __forceinline__ unsigned long long dup2(float v) {
    unsigned long long r;
    unsigned u = __float_as_uint(v);
    asm("mov.b64 %0, {%1, %1};" : "=l"(r) : "r"(u));
    return r;
}
__device__ __forceinline__ float2 unpack2(unsigned long long v) {
    unsigned lo, hi;
    asm("mov.b64 {%0, %1}, %2;" : "=r"(lo), "=r"(hi) : "l"(v));
    return make_float2(__uint_as_float(lo), __uint_as_float(hi));
}

// ---------------- baseline-PTX tensor helpers ----------------
__device__ __forceinline__ uint32_t smem_u32(const void* p) {
    uint32_t a;
    asm("{ .reg .u64 t; cvta.to.shared.u64 t, %1; cvt.u32.u64 %0, t; }" : "=r"(a) : "l"(p));
    return a;
}
__device__ __forceinline__ void cp_async16(uint32_t smem_dst, const void* gsrc) {
    asm volatile("cp.async.cg.shared.global [%0], [%1], 16;"
                 :: "r"(smem_dst), "l"(gsrc) : "memory");
}
#define CP_COMMIT() asm volatile("cp.async.commit_group;" ::: "memory")
#define CP_WAIT1() asm volatile("cp.async.wait_group 1;" ::: "memory")
#define CP_WAIT0() asm volatile("cp.async.wait_group 0;" ::: "memory")

__device__ __forceinline__ void ldmx4(uint32_t* r, uint32_t addr) {
    asm volatile("ldmatrix.sync.aligned.m8n8.x4.shared.b16 {%0,%1,%2,%3}, [%4];"
                 : "=r"(r[0]), "=r"(r[1]), "=r"(r[2]), "=r"(r[3]) : "r"(addr));
}
__device__ __forceinline__ void mma16816(float* c, const uint32_t* a, uint32_t b0, uint32_t b1) {
    asm volatile("mma.sync.aligned.m16n8k16.row.col.f32.f16.f16.f32 "
                 "{%0,%1,%2,%3}, {%4,%5,%6,%7}, {%8,%9}, {%0,%1,%2,%3};"
                 : "+f"(c[0]), "+f"(c[1]), "+f"(c[2]), "+f"(c[3])
                 : "r"(a[0]), "r"(a[1]), "r"(a[2]), "r"(a[3]), "r"(b0), "r"(b1));
}

#define SWZ(o) ((o) ^ (((o) >> 3) & 0x70))

// ---------------- prep: fold weights/bias + fp16 convert + step-1 h/c ----------------
__global__ void prep_w(const float* __restrict__ Wih, const float* __restrict__ Whh,
                       const float* __restrict__ bih, const float* __restrict__ bhh) {
    int t = blockIdx.x * blockDim.x + threadIdx.x;
    if (t < 1024) g_b[t] = bih[t] + bhh[t];
    if (t < 256) {                       // step-1 h/c: q_star = h = c = 0 -> gates = b
        float bi = bih[t] + bhh[t];
        float bg = bih[512 + t] + bhh[512 + t];
        float bo = bih[768 + t] + bhh[768 + t];
        float c = sigf(bi) * tanhf(bg);
        g_c0[t] = c;
        g_h0[t] = sigf(bo) * tanhf(c);
    }
    if (t < 1024 * 512) {
        int g = t >> 9, k = t & 511;
        float v = Wih[t];
        if (k < 256) v += Whh[g * 256 + k];
        g_Wh[t] = __float2half_rn(v);
    }
}

// ---------------- segment boundaries ----------------
__global__ void seg_bounds(const int* __restrict__ idx32) {
    int b = blockIdx.x * blockDim.x + threadIdx.x;
    if (b > BB) return;
    bool is64 = (idx32[NN - 1] == 0);
    int lo = 0, hi = NN;
    while (lo < hi) {
        int mid = (lo + hi) >> 1;
        int v = is64 ? idx32[2 * mid] : idx32[mid];
        if (v < b) lo = mid + 1; else hi = mid;
    }
    g_seg[b] = lo;
}

// ---------------- shared attn combine epilogue ----------------
__device__ __forceinline__ void attn_combine(int b, int w, int lane,
                                             float m, float z, const float* rr) {
    __shared__ float sm[8], sz[8];
    __shared__ float sr[8][256];
    *(float4*)&sr[w][4 * lane]       = *(const float4*)&rr[0];
    *(float4*)&sr[w][128 + 4 * lane] = *(const float4*)&rr[4];
    if (lane == 0) { sm[w] = m; sz[w] = z; }
    __syncthreads();
    int d = threadIdx.x;
    float M = -INFINITY;
#pragma unroll
    for (int ww = 0; ww < 8; ww++) M = fmaxf(M, sm[ww]);
    float outv = 0.f;
    if (M != -INFINITY) {
        float Z = 0.f, v = 0.f;
#pragma unroll
        for (int ww = 0; ww < 8; ww++) {
            float sc = __expf(sm[ww] - M);
            Z += sc * sz[ww];
            v += sc * sr[ww][d];
        }
        outv = v / Z;
    }
    g_hr[b * 512 + 256 + d] = outv;
    g_Ah[b * 512 + 256 + d] = __float2half_rn(outv);
}

// ---------------- attn step 1: fp32 x read, writes fp16 cache; q = h0 ----------------
__global__ void __launch_bounds__(256) attn1(const float* __restrict__ x) {
    int b = blockIdx.x;
    int s = g_seg[b], e = g_seg[b + 1];
    int lane = threadIdx.x & 31, w = threadIdx.x >> 5;

    __shared__ float q_s[256];
    {
        int d = threadIdx.x;
        float h = g_h0[d];
        g_hr[b * 512 + d] = h;
        g_Ah[b * 512 + d] = __float2half_rn(h);
        g_c[b * 256 + d] = g_c0[d];
        q_s[d] = h;
    }
    __syncthreads();

    float4 qa = *(const float4*)&q_s[4 * lane];
    float4 qb = *(const float4*)&q_s[128 + 4 * lane];

    float m = -INFINITY, z = 0.f;
    float rr[8];
#pragma unroll
    for (int j = 0; j < 8; j++) rr[j] = 0.f;

    uint4* xc = (uint4*)g_x16;
    for (int n = s + 2 * w; n < e; n += 16) {
        const float4* x0 = (const float4*)&x[(size_t)n * DD];
        float4 xa0 = x0[lane];
        float4 xb0 = x0[32 + lane];
        bool has2 = (n + 1) < e;
        float4 xa1 = {0.f, 0.f, 0.f, 0.f}, xb1 = {0.f, 0.f, 0.f, 0.f};
        if (has2) {
            const float4* x1 = (const float4*)&x[(size_t)(n + 1) * DD];
            xa1 = x1[lane];
            xb1 = x1[32 + lane];
        }
        // write fp16 cache (lane-permuted: lane owns dims {4l..4l+3, 128+4l..128+4l+3})
        {
            uint4 pv;
            __half2* ph = (__half2*)&pv;
            ph[0] = __floats2half2_rn(xa0.x, xa0.y);
            ph[1] = __floats2half2_rn(xa0.z, xa0.w);
            ph[2] = __floats2half2_rn(xb0.x, xb0.y);
            ph[3] = __floats2half2_rn(xb0.z, xb0.w);
            xc[(size_t)n * 32 + lane] = pv;
            if (has2) {
                ph[0] = __floats2half2_rn(xa1.x, xa1.y);
                ph[1] = __floats2half2_rn(xa1.z, xa1.w);
                ph[2] = __floats2half2_rn(xb1.x, xb1.y);
                ph[3] = __floats2half2_rn(xb1.z, xb1.w);
                xc[(size_t)(n + 1) * 32 + lane] = pv;
            }
        }
        float p0 = xa0.x * qa.x + xa0.y * qa.y + xa0.z * qa.z + xa0.w * qa.w
                 + xb0.x * qb.x + xb0.y * qb.y + xb0.z * qb.z + xb0.w * qb.w;
        float p1 = xa1.x * qa.x + xa1.y * qa.y + xa1.z * qa.z + xa1.w * qa.w
                 + xb1.x * qb.x + xb1.y * qb.y + xb1.z * qb.z + xb1.w * qb.w;
#pragma unroll
        for (int o = 16; o; o >>= 1) {
            p0 += __shfl_xor_sync(0xffffffff, p0, o);
            p1 += __shfl_xor_sync(0xffffffff, p1, o);
        }
        float e1v = has2 ? p1 : -INFINITY;
        float newm = fmaxf(m, fmaxf(p0, e1v));
        float sc = __expf(m - newm);
        float a0 = __expf(p0 - newm);
        float a1 = __expf(e1v - newm);
        z = z * sc + a0 + a1;
        rr[0] = rr[0] * sc + a0 * xa0.x + a1 * xa1.x;
        rr[1] = rr[1] * sc + a0 * xa0.y + a1 * xa1.y;
        rr[2] = rr[2] * sc + a0 * xa0.z + a1 * xa1.z;
        rr[3] = rr[3] * sc + a0 * xa0.w + a1 * xa1.w;
        rr[4] = rr[4] * sc + a0 * xb0.x + a1 * xb1.x;
        rr[5] = rr[5] * sc + a0 * xb0.y + a1 * xb1.y;
        rr[6] = rr[6] * sc + a0 * xb0.z + a1 * xb1.z;
        rr[7] = rr[7] * sc + a0 * xb0.w + a1 * xb1.w;
        m = newm;
    }
    attn_combine(b, w, lane, m, z, rr);
}

// ---------------- attn steps 2/3: fused LSTM pointwise + fp16 x, 4-node unroll ------
__global__ void __launch_bounds__(256) attn23() {
    int b = blockIdx.x;
    int s = g_seg[b], e = g_seg[b + 1];
    int lane = threadIdx.x & 31, w = threadIdx.x >> 5;

    __shared__ float q_s[256];
    {
        int d = threadIdx.x;
        const float* g = g_gates + b * 1024;
        float i  = g[d]       + g_b[d];
        float f  = g[256 + d] + g_b[256 + d];
        float gg = g[512 + d] + g_b[512 + d];
        float o  = g[768 + d] + g_b[768 + d];
        float c = sigf(f) * g_c[b * 256 + d] + sigf(i) * tanhf(gg);
        g_c[b * 256 + d] = c;
        float h = sigf(o) * tanhf(c);
        g_hr[b * 512 + d] = h;
        g_Ah[b * 512 + d] = __float2half_rn(h);
        q_s[d] = h;
    }
    __syncthreads();

    float qf[8];
    *(float4*)&qf[0] = *(const float4*)&q_s[4 * lane];
    *(float4*)&qf[4] = *(const float4*)&q_s[128 + 4 * lane];

    float m = -INFINITY, z = 0.f;
    float rr[8];
#pragma unroll
    for (int j = 0; j < 8; j++) rr[j] = 0.f;

    const uint4* xc = (const uint4*)g_x16;
    for (int n0 = s + 4 * w; n0 < e; n0 += 32) {
        float xf[4][8];
        float p[4];
#pragma unroll
        for (int i = 0; i < 4; i++) {
            int n = n0 + i;
            uint4 v = make_uint4(0u, 0u, 0u, 0u);
            if (n < e) v = xc[(size_t)n * 32 + lane];
            const __half2* ph = (const __half2*)&v;
            float2 f0 = __half22float2(ph[0]);
            float2 f1 = __half22float2(ph[1]);
            float2 f2 = __half22float2(ph[2]);
            float2 f3 = __half22float2(ph[3]);
            xf[i][0] = f0.x; xf[i][1] = f0.y; xf[i][2] = f1.x; xf[i][3] = f1.y;
            xf[i][4] = f2.x; xf[i][5] = f2.y; xf[i][6] = f3.x; xf[i][7] = f3.y;
            p[i] = xf[i][0] * qf[0] + xf[i][1] * qf[1] + xf[i][2] * qf[2] + xf[i][3] * qf[3]
                 + xf[i][4] * qf[4] + xf[i][5] * qf[5] + xf[i][6] * qf[6] + xf[i][7] * qf[7];
        }
#pragma unroll
        for (int o = 16; o; o >>= 1) {
#pragma unroll
            for (int i = 0; i < 4; i++)
                p[i] += __shfl_xor_sync(0xffffffff, p[i], o);
        }
        float e0 = p[0];
        float e1 = (n0 + 1 < e) ? p[1] : -INFINITY;
        float e2 = (n0 + 2 < e) ? p[2] : -INFINITY;
        float e3 = (n0 + 3 < e) ? p[3] : -INFINITY;
        float newm = fmaxf(m, fmaxf(fmaxf(e0, e1), fmaxf(e2, e3)));
        float sc = __expf(m - newm);
        float a0 = __expf(e0 - newm);
        float a1 = __expf(e1 - newm);
        float a2 = __expf(e2 - newm);
        float a3 = __expf(e3 - newm);
        z = z * sc + a0 + a1 + a2 + a3;
#pragma unroll
        for (int j = 0; j < 8; j++)
            rr[j] = rr[j] * sc + a0 * xf[0][j] + a1 * xf[1][j] + a2 * xf[2][j] + a3 * xf[3][j];
        m = newm;
    }
    attn_combine(b, w, lane, m, z, rr);
}

// ---------------- gates GEMM via mma.sync fp16 (HMMA), single-term K=512 ----------
// C[m][n] = Ah16·Wh16. CTA tile 128x128, 8 chunks of K=64, cp.async
// 3-stage pipeline, one __syncthreads per chunk. 8 warps: 2(m) x 4(n).
__global__ void __launch_bounds__(256) gemm_gates_mma() {
    extern __shared__ char dsm[];   // 3 stages x (16KB A + 16KB B)

    int tid = threadIdx.x, wid = tid >> 5, lane = tid & 31;
    int bm = blockIdx.y * 128, bn = blockIdx.x * 128;

    int srow = tid >> 1, shalf = tid & 1;
    int sbase = srow * 128 + shalf * 64;

    float acc[4][4][4];
#pragma unroll
    for (int i = 0; i < 4; i++)
#pragma unroll
        for (int j = 0; j < 4; j++)
#pragma unroll
            for (int q = 0; q < 4; q++) acc[i][j][q] = 0.f;

    auto issue = [&](int c, int st) {
        int kb = c * 64;
        const __half* As = g_Ah + (size_t)(bm + srow) * 512 + kb + shalf * 32;
        const __half* Bs = g_Wh + (size_t)(bn + srow) * 512 + kb + shalf * 32;
        uint32_t ua = smem_u32(dsm + st * 32768);
        uint32_t ub = ua + 16384;
#pragma unroll
        for (int j = 0; j < 4; j++) {
            cp_async16(ua + SWZ(sbase + j * 16), (const char*)As + j * 16);
            cp_async16(ub + SWZ(sbase + j * 16), (const char*)Bs + j * 16);
        }
        CP_COMMIT();
    };

    issue(0, 0);
    issue(1, 1);

    int wm = (wid >> 2) * 64;
    int wn = (wid & 3) * 32;
    int a_row = (lane & 7) + 8 * ((lane >> 3) & 1);
    int a_colB = (lane >> 4) * 16;
    int b_row = ((lane >> 4) << 3) + (lane & 7);
    int b_colB = ((lane >> 3) & 1) * 16;

    for (int c = 0; c < 8; c++) {
        if (c == 7) { CP_WAIT0(); } else { CP_WAIT1(); }
        __syncthreads();
        if (c + 2 < 8) issue(c + 2, (c + 2) % 3);
        uint32_t ua = smem_u32(dsm + (c % 3) * 32768);
        uint32_t ub = ua + 16384;
#pragma unroll
        for (int kk = 0; kk < 4; kk++) {
            int kB = kk * 32;
            uint32_t a[4][4];
#pragma unroll
            for (int mt = 0; mt < 4; mt++)
                ldmx4(a[mt], ua + SWZ((wm + mt * 16 + a_row) * 128 + a_colB + kB));
            uint32_t bfr[2][4];
#pragma unroll
            for (int nt = 0; nt < 2; nt++)
                ldmx4(bfr[nt], ub + SWZ((wn + nt * 16 + b_row) * 128 + b_colB + kB));
#pragma unroll
            for (int mt = 0; mt < 4; mt++) {
#pragma unroll
                for (int nt = 0; nt < 4; nt++) {
                    uint32_t b0 = bfr[nt >> 1][(nt & 1) * 2];
                    uint32_t b1 = bfr[nt >> 1][(nt & 1) * 2 + 1];
                    mma16816(acc[mt][nt], a[mt], b0, b1);
                }
            }
        }
    }

    __syncthreads();
    int g = lane >> 2, n0 = (lane & 3) * 2;
#pragma unroll
    for (int mt = 0; mt < 4; mt++) {
#pragma unroll
        for (int nt = 0; nt < 4; nt++) {
            int row = bm + wm + mt * 16 + g;
            int col = bn + wn + nt * 8 + n0;
            *(float2*)&g_gates[(size_t)row * 1024 + col] =
                make_float2(acc[mt][nt][0], acc[mt][nt][1]);
            *(float2*)&g_gates[(size_t)(row + 8) * 1024 + col] =
                make_float2(acc[mt][nt][2], acc[mt][nt][3]);
        }
    }
}

// ---------------- output GEMM: 64x64 tile, BK=8, f32x2 ----------------
__global__ void __launch_bounds__(256) gemm_out64(const float* __restrict__ Wp,
                                                  const float* __restrict__ bp,
                                                  float* __restrict__ out) {
    const int K = 512, LDC = 256;
    __shared__ float As[2][8][68];
    __shared__ float Bs[2][8][68];
    int tid = threadIdx.x;
    int bm = blockIdx.y * 64, bn = blockIdx.x * 64;
    int lr = tid >> 2, lc = (tid & 3) << 1;
    int tx = tid & 15, ty = tid >> 4;
    const float* Ag = g_hr + (size_t)(bm + lr) * K + lc;
    const float* Bg = Wp + (size_t)(bn + lr) * K + lc;

    unsigned long long acc[2][4];
#pragma unroll
    for (int i = 0; i < 2; i++)
#pragma unroll
        for (int j = 0; j < 4; j++) acc[i][j] = 0ull;

    float2 a2 = *(const float2*)Ag;
    float2 b2 = *(const float2*)Bg;
    As[0][lc][lr] = a2.x; As[0][lc + 1][lr] = a2.y;
    Bs[0][lc][lr] = b2.x; Bs[0][lc + 1][lr] = b2.y;
    __syncthreads();

    int buf = 0;
    for (int k0 = 0; k0 < K; k0 += 8) {
        bool more = (k0 + 8) < K;
        if (more) {
            a2 = *(const float2*)(Ag + k0 + 8);
            b2 = *(const float2*)(Bg + k0 + 8);
        }
#pragma unroll
        for (int k = 0; k < 8; k++) {
            float4 a0 = *(const float4*)&As[buf][k][ty * 4];
            float4 b0 = *(const float4*)&Bs[buf][k][tx * 4];
            unsigned long long ap[2] = { pack2(a0.x, a0.y), pack2(a0.z, a0.w) };
            unsigned long long bd[4] = { dup2(b0.x), dup2(b0.y), dup2(b0.z), dup2(b0.w) };
#pragma unroll
            for (int i = 0; i < 2; i++)
#pragma unroll
                for (int j = 0; j < 4; j++)
                    fma2(acc[i][j], ap[i], bd[j]);
        }
        if (more) {
            As[buf ^ 1][lc][lr] = a2.x; As[buf ^ 1][lc + 1][lr] = a2.y;
            Bs[buf ^ 1][lc][lr] = b2.x; Bs[buf ^ 1][lc + 1][lr] = b2.y;
        }
        __syncthreads();
        buf ^= 1;
    }

    float4 bias4 = *(const float4*)&bp[bn + tx * 4];
    int rbase[2] = { ty * 4, ty * 4 + 2 };
#pragma unroll
    for (int i = 0; i < 2; i++) {
        float4 lo, hi;
        float2 u;
        u = unpack2(acc[i][0]); lo.x = u.x; hi.x = u.y;
        u = unpack2(acc[i][1]); lo.y = u.x; hi.y = u.y;
        u = unpack2(acc[i][2]); lo.z = u.x; hi.z = u.y;
        u = unpack2(acc[i][3]); lo.w = u.x; hi.w = u.y;
        lo.x += bias4.x; lo.y += bias4.y; lo.z += bias4.z; lo.w += bias4.w;
        hi.x += bias4.x; hi.y += bias4.y; hi.z += bias4.z; hi.w += bias4.w;
        int r0 = bm + rbase[i];
        *(float4*)&out[(size_t)r0 * LDC + bn + tx * 4] = lo;
        *(float4*)&out[(size_t)(r0 + 1) * LDC + bn + tx * 4] = hi;
    }
}

// ---------------- launch ----------------
extern "C" void kernel_launch(void* const* d_in, const int* in_sizes, int n_in,
                              void* d_out, int out_size) {
    const float* x     = (const float*)d_in[0];
    const int*   idx32 = (const int*)d_in[1];
    const float* Wih   = (const float*)d_in[2];
    const float* Whh   = (const float*)d_in[3];
    const float* bih   = (const float*)d_in[4];
    const float* bhh   = (const float*)d_in[5];
    const float* Wp    = (const float*)d_in[6];
    const float* bp    = (const float*)d_in[7];
    float* out = (float*)d_out;

    const int GEMM_DSM = 3 * 32768;   // 96 KB
    cudaFuncSetAttribute(gemm_gates_mma, cudaFuncAttributeMaxDynamicSharedMemorySize, GEMM_DSM);

    prep_w<<<(1024 * 512 + 255) / 256, 256>>>(Wih, Whh, bih, bhh);
    seg_bounds<<<(BB + 1 + 255) / 256, 256>>>(idx32);
    attn1<<<BB, 256>>>(x);                                  // step 1 + fp16 cache fill

    for (int t = 0; t < 2; t++) {                           // steps 2, 3
        gemm_gates_mma<<<dim3(8, 16), 256, GEMM_DSM>>>();
        attn23<<<BB, 256>>>();
    }
    gemm_out64<<<dim3(4, 32), 256>>>(Wp, bp, out);
}

// round 14
// speedup vs baseline: 1.2048x; 1.0078x over previous
#include <cuda_runtime.h>
#include <cuda_fp16.h>
#include <math.h>
#include <stdint.h>

#define NN 400000
#define DD 256
#define BB 2048

// ---------------- scratch (static device globals; no allocation) ----------------
__device__ float g_hr[BB * 512];            // [h | r] per segment row
__device__ float g_c[BB * DD];              // LSTM cell state
__device__ float g_gates[BB * 1024];        // pre-activation gates
__device__ float g_b[1024];                 // bih + bhh
__device__ float g_h0[256];                 // step-1 h (same for all segments)
__device__ float g_c0[256];                 // step-1 c
__device__ int   g_seg[BB + 1];             // segment boundaries
__device__ __half g_Ah[BB * 512];           // hr (fp16) for HMMA
__device__ __half g_Wh[1024 * 512];         // folded W (fp16)
__device__ __align__(16) __half g_x16[(size_t)NN * DD];  // fp16 cache of x (lane-permuted)

__device__ __forceinline__ float sigf(float v) { return 1.f / (1.f + __expf(-v)); }

// ---------------- packed fp32x2 helpers ----------------
__device__ __forceinline__ void fma2(unsigned long long& d, unsigned long long a,
                                     unsigned long long b) {
    asm("fma.rn.f32x2 %0, %1, %2, %0;" : "+l"(d) : "l"(a), "l"(b));
}
__device__ __forceinline__ unsigned long long pack2(float lo, float hi) {
    unsigned long long r;
    asm("mov.b64 %0, {%1, %2};" : "=l"(r)
        : "r"(__float_as_uint(lo)), "r"(__float_as_uint(hi)));
    return r;
}
__device__ __forceinline__ unsigned long long dup2(float v) {
    unsigned long long r;
    unsigned u = __float_as_uint(v);
    asm("mov.b64 %0, {%1, %1};" : "=l"(r) : "r"(u));
    return r;
}
__device__ __forceinline__ float2 unpack2(unsigned long long v) {
    unsigned lo, hi;
    asm("mov.b64 {%0, %1}, %2;" : "=r"(lo), "=r"(hi) : "l"(v));
    return make_float2(__uint_as_float(lo), __uint_as_float(hi));
}

// ---------------- baseline-PTX tensor helpers ----------------
__device__ __forceinline__ uint32_t smem_u32(const void* p) {
    uint32_t a;
    asm("{ .reg .u64 t; cvta.to.shared.u64 t, %1; cvt.u32.u64 %0, t; }" : "=r"(a) : "l"(p));
    return a;
}
__device__ __forceinline__ void cp_async16(uint32_t smem_dst, const void* gsrc) {
    asm volatile("cp.async.cg.shared.global [%0], [%1], 16;"
                 :: "r"(smem_dst), "l"(gsrc) : "memory");
}
#define CP_COMMIT() asm volatile("cp.async.commit_group;" ::: "memory")
#define CP_WAIT1() asm volatile("cp.async.wait_group 1;" ::: "memory")
#define CP_WAIT0() asm volatile("cp.async.wait_group 0;" ::: "memory")

__device__ __forceinline__ void ldmx4(uint32_t* r, uint32_t addr) {
    asm volatile("ldmatrix.sync.aligned.m8n8.x4.shared.b16 {%0,%1,%2,%3}, [%4];"
                 : "=r"(r[0]), "=r"(r[1]), "=r"(r[2]), "=r"(r[3]) : "r"(addr));
}
__device__ __forceinline__ void mma16816(float* c, const uint32_t* a, uint32_t b0, uint32_t b1) {
    asm volatile("mma.sync.aligned.m16n8k16.row.col.f32.f16.f16.f32 "
                 "{%0,%1,%2,%3}, {%4,%5,%6,%7}, {%8,%9}, {%0,%1,%2,%3};"
                 : "+f"(c[0]), "+f"(c[1]), "+f"(c[2]), "+f"(c[3])
                 : "r"(a[0]), "r"(a[1]), "r"(a[2]), "r"(a[3]), "r"(b0), "r"(b1));
}

#define SWZ(o) ((o) ^ (((o) >> 3) & 0x70))

// ---------------- prep: fold weights/bias + fp16 convert + step-1 h/c + seg bounds ----
__global__ void prep_w(const float* __restrict__ Wih, const float* __restrict__ Whh,
                       const float* __restrict__ bih, const float* __restrict__ bhh,
                       const int* __restrict__ idx32) {
    int t = blockIdx.x * blockDim.x + threadIdx.x;
    if (t < 1024) g_b[t] = bih[t] + bhh[t];
    if (t < 256) {                       // step-1 h/c: q_star = h = c = 0 -> gates = b
        float bi = bih[t] + bhh[t];
        float bg = bih[512 + t] + bhh[512 + t];
        float bo = bih[768 + t] + bhh[768 + t];
        float c = sigf(bi) * tanhf(bg);
        g_c0[t] = c;
        g_h0[t] = sigf(bo) * tanhf(c);
    }
    if (t <= BB) {                       // segment boundaries (sorted index, int32/int64)
        bool is64 = (idx32[NN - 1] == 0);
        int lo = 0, hi = NN;
        while (lo < hi) {
            int mid = (lo + hi) >> 1;
            int v = is64 ? idx32[2 * mid] : idx32[mid];
            if (v < t) lo = mid + 1; else hi = mid;
        }
        g_seg[t] = lo;
    }
    if (t < 1024 * 512) {
        int g = t >> 9, k = t & 511;
        float v = Wih[t];
        if (k < 256) v += Whh[g * 256 + k];
        g_Wh[t] = __float2half_rn(v);
    }
}

// ---------------- shared attn combine epilogue ----------------
__device__ __forceinline__ void attn_combine(int b, int w, int lane,
                                             float m, float z, const float* rr) {
    __shared__ float sm[8], sz[8];
    __shared__ float sr[8][256];
    *(float4*)&sr[w][4 * lane]       = *(const float4*)&rr[0];
    *(float4*)&sr[w][128 + 4 * lane] = *(const float4*)&rr[4];
    if (lane == 0) { sm[w] = m; sz[w] = z; }
    __syncthreads();
    int d = threadIdx.x;
    float M = -INFINITY;
#pragma unroll
    for (int ww = 0; ww < 8; ww++) M = fmaxf(M, sm[ww]);
    float outv = 0.f;
    if (M != -INFINITY) {
        float Z = 0.f, v = 0.f;
#pragma unroll
        for (int ww = 0; ww < 8; ww++) {
            float sc = __expf(sm[ww] - M);
            Z += sc * sz[ww];
            v += sc * sr[ww][d];
        }
        outv = v / Z;
    }
    g_hr[b * 512 + 256 + d] = outv;
    g_Ah[b * 512 + 256 + d] = __float2half_rn(outv);
}

// ---------------- attn step 1: fp32 x read, writes fp16 cache; q = h0 ----------------
__global__ void __launch_bounds__(256) attn1(const float* __restrict__ x) {
    int b = blockIdx.x;
    int s = g_seg[b], e = g_seg[b + 1];
    int lane = threadIdx.x & 31, w = threadIdx.x >> 5;

    __shared__ float q_s[256];
    {
        int d = threadIdx.x;
        float h = g_h0[d];
        g_hr[b * 512 + d] = h;
        g_Ah[b * 512 + d] = __float2half_rn(h);
        g_c[b * 256 + d] = g_c0[d];
        q_s[d] = h;
    }
    __syncthreads();

    float4 qa = *(const float4*)&q_s[4 * lane];
    float4 qb = *(const float4*)&q_s[128 + 4 * lane];

    float m = -INFINITY, z = 0.f;
    float rr[8];
#pragma unroll
    for (int j = 0; j < 8; j++) rr[j] = 0.f;

    uint4* xc = (uint4*)g_x16;
    for (int n = s + 2 * w; n < e; n += 16) {
        const float4* x0 = (const float4*)&x[(size_t)n * DD];
        float4 xa0 = x0[lane];
        float4 xb0 = x0[32 + lane];
        bool has2 = (n + 1) < e;
        float4 xa1 = {0.f, 0.f, 0.f, 0.f}, xb1 = {0.f, 0.f, 0.f, 0.f};
        if (has2) {
            const float4* x1 = (const float4*)&x[(size_t)(n + 1) * DD];
            xa1 = x1[lane];
            xb1 = x1[32 + lane];
        }
        // write fp16 cache (lane-permuted: lane owns dims {4l..4l+3, 128+4l..128+4l+3})
        {
            uint4 pv;
            __half2* ph = (__half2*)&pv;
            ph[0] = __floats2half2_rn(xa0.x, xa0.y);
            ph[1] = __floats2half2_rn(xa0.z, xa0.w);
            ph[2] = __floats2half2_rn(xb0.x, xb0.y);
            ph[3] = __floats2half2_rn(xb0.z, xb0.w);
            xc[(size_t)n * 32 + lane] = pv;
            if (has2) {
                ph[0] = __floats2half2_rn(xa1.x, xa1.y);
                ph[1] = __floats2half2_rn(xa1.z, xa1.w);
                ph[2] = __floats2half2_rn(xb1.x, xb1.y);
                ph[3] = __floats2half2_rn(xb1.z, xb1.w);
                xc[(size_t)(n + 1) * 32 + lane] = pv;
            }
        }
        float p0 = xa0.x * qa.x + xa0.y * qa.y + xa0.z * qa.z + xa0.w * qa.w
                 + xb0.x * qb.x + xb0.y * qb.y + xb0.z * qb.z + xb0.w * qb.w;
        float p1 = xa1.x * qa.x + xa1.y * qa.y + xa1.z * qa.z + xa1.w * qa.w
                 + xb1.x * qb.x + xb1.y * qb.y + xb1.z * qb.z + xb1.w * qb.w;
#pragma unroll
        for (int o = 16; o; o >>= 1) {
            p0 += __shfl_xor_sync(0xffffffff, p0, o);
            p1 += __shfl_xor_sync(0xffffffff, p1, o);
        }
        float e1v = has2 ? p1 : -INFINITY;
        float newm = fmaxf(m, fmaxf(p0, e1v));
        float sc = __expf(m - newm);
        float a0 = __expf(p0 - newm);
        float a1 = __expf(e1v - newm);
        z = z * sc + a0 + a1;
        rr[0] = rr[0] * sc + a0 * xa0.x + a1 * xa1.x;
        rr[1] = rr[1] * sc + a0 * xa0.y + a1 * xa1.y;
        rr[2] = rr[2] * sc + a0 * xa0.z + a1 * xa1.z;
        rr[3] = rr[3] * sc + a0 * xa0.w + a1 * xa1.w;
        rr[4] = rr[4] * sc + a0 * xb0.x + a1 * xb1.x;
        rr[5] = rr[5] * sc + a0 * xb0.y + a1 * xb1.y;
        rr[6] = rr[6] * sc + a0 * xb0.z + a1 * xb1.z;
        rr[7] = rr[7] * sc + a0 * xb0.w + a1 * xb1.w;
        m = newm;
    }
    attn_combine(b, w, lane, m, z, rr);
}

// ---------------- attn steps 2/3: fused LSTM pointwise + fp16 x, 4-node unroll ------
__global__ void __launch_bounds__(256) attn23() {
    int b = blockIdx.x;
    int s = g_seg[b], e = g_seg[b + 1];
    int lane = threadIdx.x & 31, w = threadIdx.x >> 5;

    __shared__ float q_s[256];
    {
        int d = threadIdx.x;
        const float* g = g_gates + b * 1024;
        float i  = g[d]       + g_b[d];
        float f  = g[256 + d] + g_b[256 + d];
        float gg = g[512 + d] + g_b[512 + d];
        float o  = g[768 + d] + g_b[768 + d];
        float c = sigf(f) * g_c[b * 256 + d] + sigf(i) * tanhf(gg);
        g_c[b * 256 + d] = c;
        float h = sigf(o) * tanhf(c);
        g_hr[b * 512 + d] = h;
        g_Ah[b * 512 + d] = __float2half_rn(h);
        q_s[d] = h;
    }
    __syncthreads();

    float qf[8];
    *(float4*)&qf[0] = *(const float4*)&q_s[4 * lane];
    *(float4*)&qf[4] = *(const float4*)&q_s[128 + 4 * lane];

    float m = -INFINITY, z = 0.f;
    float rr[8];
#pragma unroll
    for (int j = 0; j < 8; j++) rr[j] = 0.f;

    const uint4* xc = (const uint4*)g_x16;
    for (int n0 = s + 4 * w; n0 < e; n0 += 32) {
        float xf[4][8];
        float p[4];
#pragma unroll
        for (int i = 0; i < 4; i++) {
            int n = n0 + i;
            uint4 v = make_uint4(0u, 0u, 0u, 0u);
            if (n < e) v = xc[(size_t)n * 32 + lane];
            const __half2* ph = (const __half2*)&v;
            float2 f0 = __half22float2(ph[0]);
            float2 f1 = __half22float2(ph[1]);
            float2 f2 = __half22float2(ph[2]);
            float2 f3 = __half22float2(ph[3]);
            xf[i][0] = f0.x; xf[i][1] = f0.y; xf[i][2] = f1.x; xf[i][3] = f1.y;
            xf[i][4] = f2.x; xf[i][5] = f2.y; xf[i][6] = f3.x; xf[i][7] = f3.y;
            p[i] = xf[i][0] * qf[0] + xf[i][1] * qf[1] + xf[i][2] * qf[2] + xf[i][3] * qf[3]
                 + xf[i][4] * qf[4] + xf[i][5] * qf[5] + xf[i][6] * qf[6] + xf[i][7] * qf[7];
        }
#pragma unroll
        for (int o = 16; o; o >>= 1) {
#pragma unroll
            for (int i = 0; i < 4; i++)
                p[i] += __shfl_xor_sync(0xffffffff, p[i], o);
        }
        float e0 = p[0];
        float e1 = (n0 + 1 < e) ? p[1] : -INFINITY;
        float e2 = (n0 + 2 < e) ? p[2] : -INFINITY;
        float e3 = (n0 + 3 < e) ? p[3] : -INFINITY;
        float newm = fmaxf(m, fmaxf(fmaxf(e0, e1), fmaxf(e2, e3)));
        float sc = __expf(m - newm);
        float a0 = __expf(e0 - newm);
        float a1 = __expf(e1 - newm);
        float a2 = __expf(e2 - newm);
        float a3 = __expf(e3 - newm);
        z = z * sc + a0 + a1 + a2 + a3;
#pragma unroll
        for (int j = 0; j < 8; j++)
            rr[j] = rr[j] * sc + a0 * xf[0][j] + a1 * xf[1][j] + a2 * xf[2][j] + a3 * xf[3][j];
        m = newm;
    }
    attn_combine(b, w, lane, m, z, rr);
}

// ---------------- gates GEMM via mma.sync fp16 (HMMA), single-term K=512 ----------
// C[m][n] = Ah16·Wh16. CTA tile 128x128, 4 pair-chunks of K=128 (two 64-col panels
// per stage), 3 pair-stages x 64KB = 192KB smem, one wait+sync per pair-chunk.
// 8 warps: 2(m) x 4(n).
__global__ void __launch_bounds__(256) gemm_gates_mma() {
    extern __shared__ char dsm[];   // 3 stages x (A panel0|A panel1|B panel0|B panel1)

    int tid = threadIdx.x, wid = tid >> 5, lane = tid & 31;
    int bm = blockIdx.y * 128, bn = blockIdx.x * 128;

    int srow = tid >> 1, shalf = tid & 1;
    int sbase = srow * 128 + shalf * 64;

    float acc[4][4][4];
#pragma unroll
    for (int i = 0; i < 4; i++)
#pragma unroll
        for (int j = 0; j < 4; j++)
#pragma unroll
            for (int q = 0; q < 4; q++) acc[i][j][q] = 0.f;

    auto issue_pair = [&](int p, int st) {
        char* base = dsm + st * 65536;
#pragma unroll
        for (int sub = 0; sub < 2; sub++) {
            int kb = p * 128 + sub * 64;
            const __half* As = g_Ah + (size_t)(bm + srow) * 512 + kb + shalf * 32;
            const __half* Bs = g_Wh + (size_t)(bn + srow) * 512 + kb + shalf * 32;
            uint32_t ua = smem_u32(base + sub * 16384);
            uint32_t ub = smem_u32(base + 32768 + sub * 16384);
#pragma unroll
            for (int j = 0; j < 4; j++) {
                cp_async16(ua + SWZ(sbase + j * 16), (const char*)As + j * 16);
                cp_async16(ub + SWZ(sbase + j * 16), (const char*)Bs + j * 16);
            }
        }
        CP_COMMIT();
    };

    issue_pair(0, 0);
    issue_pair(1, 1);

    int wm = (wid >> 2) * 64;
    int wn = (wid & 3) * 32;
    int a_row = (lane & 7) + 8 * ((lane >> 3) & 1);
    int a_colB = (lane >> 4) * 16;
    int b_row = ((lane >> 4) << 3) + (lane & 7);
    int b_colB = ((lane >> 3) & 1) * 16;

    for (int p = 0; p < 4; p++) {
        if (p == 3) { CP_WAIT0(); } else { CP_WAIT1(); }
        __syncthreads();
        if (p + 2 < 4) issue_pair(p + 2, (p + 2) % 3);
        char* base = dsm + (p % 3) * 65536;
#pragma unroll
        for (int kk = 0; kk < 8; kk++) {
            uint32_t ua = smem_u32(base + (kk >> 2) * 16384);
            uint32_t ub = smem_u32(base + 32768 + (kk >> 2) * 16384);
            int kB = (kk & 3) * 32;
            uint32_t a[4][4];
#pragma unroll
            for (int mt = 0; mt < 4; mt++)
                ldmx4(a[mt], ua + SWZ((wm + mt * 16 + a_row) * 128 + a_colB + kB));
            uint32_t bfr[2][4];
#pragma unroll
            for (int nt = 0; nt < 2; nt++)
                ldmx4(bfr[nt], ub + SWZ((wn + nt * 16 + b_row) * 128 + b_colB + kB));
#pragma unroll
            for (int mt = 0; mt < 4; mt++) {
#pragma unroll
                for (int nt = 0; nt < 4; nt++) {
                    uint32_t b0 = bfr[nt >> 1][(nt & 1) * 2];
                    uint32_t b1 = bfr[nt >> 1][(nt & 1) * 2 + 1];
                    mma16816(acc[mt][nt], a[mt], b0, b1);
                }
            }
        }
    }

    __syncthreads();
    int g = lane >> 2, n0 = (lane & 3) * 2;
#pragma unroll
    for (int mt = 0; mt < 4; mt++) {
#pragma unroll
        for (int nt = 0; nt < 4; nt++) {
            int row = bm + wm + mt * 16 + g;
            int col = bn + wn + nt * 8 + n0;
            *(float2*)&g_gates[(size_t)row * 1024 + col] =
                make_float2(acc[mt][nt][0], acc[mt][nt][1]);
            *(float2*)&g_gates[(size_t)(row + 8) * 1024 + col] =
                make_float2(acc[mt][nt][2], acc[mt][nt][3]);
        }
    }
}

// ---------------- output GEMM: 64x64 tile, BK=8, f32x2 ----------------
__global__ void __launch_bounds__(256) gemm_out64(const float* __restrict__ Wp,
                                                  const float* __restrict__ bp,
                                                  float* __restrict__ out) {
    const int K = 512, LDC = 256;
    __shared__ float As[2][8][68];
    __shared__ float Bs[2][8][68];
    int tid = threadIdx.x;
    int bm = blockIdx.y * 64, bn = blockIdx.x * 64;
    int lr = tid >> 2, lc = (tid & 3) << 1;
    int tx = tid & 15, ty = tid >> 4;
    const float* Ag = g_hr + (size_t)(bm + lr) * K + lc;
    const float* Bg = Wp + (size_t)(bn + lr) * K + lc;

    unsigned long long acc[2][4];
#pragma unroll
    for (int i = 0; i < 2; i++)
#pragma unroll
        for (int j = 0; j < 4; j++) acc[i][j] = 0ull;

    float2 a2 = *(const float2*)Ag;
    float2 b2 = *(const float2*)Bg;
    As[0][lc][lr] = a2.x; As[0][lc + 1][lr] = a2.y;
    Bs[0][lc][lr] = b2.x; Bs[0][lc + 1][lr] = b2.y;
    __syncthreads();

    int buf = 0;
    for (int k0 = 0; k0 < K; k0 += 8) {
        bool more = (k0 + 8) < K;
        if (more) {
            a2 = *(const float2*)(Ag + k0 + 8);
            b2 = *(const float2*)(Bg + k0 + 8);
        }
#pragma unroll
        for (int k = 0; k < 8; k++) {
            float4 a0 = *(const float4*)&As[buf][k][ty * 4];
            float4 b0 = *(const float4*)&Bs[buf][k][tx * 4];
            unsigned long long ap[2] = { pack2(a0.x, a0.y), pack2(a0.z, a0.w) };
            unsigned long long bd[4] = { dup2(b0.x), dup2(b0.y), dup2(b0.z), dup2(b0.w) };
#pragma unroll
            for (int i = 0; i < 2; i++)
#pragma unroll
                for (int j = 0; j < 4; j++)
                    fma2(acc[i][j], ap[i], bd[j]);
        }
        if (more) {
            As[buf ^ 1][lc][lr] = a2.x; As[buf ^ 1][lc + 1][lr] = a2.y;
            Bs[buf ^ 1][lc][lr] = b2.x; Bs[buf ^ 1][lc + 1][lr] = b2.y;
        }
        __syncthreads();
        buf ^= 1;
    }

    float4 bias4 = *(const float4*)&bp[bn + tx * 4];
    int rbase[2] = { ty * 4, ty * 4 + 2 };
#pragma unroll
    for (int i = 0; i < 2; i++) {
        float4 lo, hi;
        float2 u;
        u = unpack2(acc[i][0]); lo.x = u.x; hi.x = u.y;
        u = unpack2(acc[i][1]); lo.y = u.x; hi.y = u.y;
        u = unpack2(acc[i][2]); lo.z = u.x; hi.z = u.y;
        u = unpack2(acc[i][3]); lo.w = u.x; hi.w = u.y;
        lo.x += bias4.x; lo.y += bias4.y; lo.z += bias4.z; lo.w += bias4.w;
        hi.x += bias4.x; hi.y += bias4.y; hi.z += bias4.z; hi.w += bias4.w;
        int r0 = bm + rbase[i];
        *(float4*)&out[(size_t)r0 * LDC + bn + tx * 4] = lo;
        *(float4*)&out[(size_t)(r0 + 1) * LDC + bn + tx * 4] = hi;
    }
}

// ---------------- launch ----------------
extern "C" void kernel_launch(void* const* d_in, const int* in_sizes, int n_in,
                              void* d_out, int out_size) {
    const float* x     = (const float*)d_in[0];
    const int*   idx32 = (const int*)d_in[1];
    const float* Wih   = (const float*)d_in[2];
    const float* Whh   = (const float*)d_in[3];
    const float* bih   = (const float*)d_in[4];
    const float* bhh   = (const float*)d_in[5];
    const float* Wp    = (const float*)d_in[6];
    const float* bp    = (const float*)d_in[7];
    float* out = (float*)d_out;

    const int GEMM_DSM = 3 * 65536;   // 192 KB
    cudaFuncSetAttribute(gemm_gates_mma, cudaFuncAttributeMaxDynamicSharedMemorySize, GEMM_DSM);

    prep_w<<<(1024 * 512 + 255) / 256, 256>>>(Wih, Whh, bih, bhh, idx32);
    attn1<<<BB, 256>>>(x);                                  // step 1 + fp16 cache fill

    for (int t = 0; t < 2; t++) {                           // steps 2, 3
        gemm_gates_mma<<<dim3(8, 16), 256, GEMM_DSM>>>();
        attn23<<<BB, 256>>>();
    }
    gemm_out64<<<dim3(4, 32), 256>>>(Wp, bp, out);
}